// round 8
// baseline (speedup 1.0000x reference)
#include <cuda_runtime.h>

typedef unsigned long long u64;

#define Bsz 256
#define Lsz 500
#define Hsz 512
#define Isz 35
#define OUTsz 35

// Scratch: encoder writes c[l][b][h]; scan converts IN-PLACE to
// h[l][b][h] = relu(b_enc + exclusive prefix); decoder reads it. 262 MB.
__device__ float g_c[(size_t)Lsz * Bsz * Hsz];

// ---- packed f32x2 helpers ----
__device__ __forceinline__ u64 fma2(u64 a, u64 b, u64 c) {
    u64 d;
    asm("fma.rn.f32x2 %0, %1, %2, %3;" : "=l"(d) : "l"(a), "l"(b), "l"(c));
    return d;
}
__device__ __forceinline__ u64 pack2(float x, float y) {
    u64 r;
    asm("mov.b64 %0, {%1, %2};" : "=l"(r) : "f"(x), "f"(y));
    return r;
}
__device__ __forceinline__ void unpack2(u64 v, float& x, float& y) {
    asm("mov.b64 {%0, %1}, %2;" : "=f"(x), "=f"(y) : "l"(v));
}
__device__ __forceinline__ unsigned smem_u32(const void* p) {
    return (unsigned)__cvta_generic_to_shared(p);
}
__device__ __forceinline__ void cp_async16(unsigned dst, const void* src) {
    asm volatile("cp.async.cg.shared.global [%0], [%1], 16;" ::
                 "r"(dst), "l"(src));
}
__device__ __forceinline__ void cp_commit() {
    asm volatile("cp.async.commit_group;");
}
template <int N>
__device__ __forceinline__ void cp_wait() {
    asm volatile("cp.async.wait_group %0;" :: "n"(N));
}

// ============================================================
// Kernel 1: encoder, 1 h-column per thread, 512-thread blocks.
// f32x2 lanes = i-pairs; W (18 u64 = 36 regs) reused over 32 b;
// x broadcast via LDS.128. grid (bq=8, l=500), block 512.
// ============================================================
__global__ void __launch_bounds__(512, 2) enc_kernel(
    const float* __restrict__ inputs,  // [B, L, 3]
    const float* __restrict__ z,       // [B, L, 32]
    const float* __restrict__ W)       // [L, 35, 512]
{
    const int bq = blockIdx.x;   // b tile (32 b)
    const int l  = blockIdx.y;
    const int t  = threadIdx.x;  // h column

    __shared__ __align__(16) float xsf[32][36];   // i padded to 36, x[35]=0

    for (int idx = t; idx < 32 * 36; idx += 512) {
        int bl = idx / 36, i = idx - bl * 36;
        int b = bq * 32 + bl;
        float v = 0.f;
        if (i < 3)       v = inputs[(b * Lsz + l) * 3 + i];
        else if (i < 35) v = z[(b * Lsz + l) * 32 + (i - 3)];
        xsf[bl][i] = v;
    }

    u64 w[18];
    const float* Wl = W + (size_t)l * Isz * Hsz;
#pragma unroll
    for (int q = 0; q < 17; q++)
        w[q] = pack2(Wl[(2 * q) * Hsz + t], Wl[(2 * q + 1) * Hsz + t]);
    w[17] = pack2(Wl[34 * Hsz + t], 0.f);    // i=35 pad (x pad = 0)
    __syncthreads();

    float* crow = &g_c[((size_t)l * Bsz + bq * 32) * Hsz + t];
    for (int bl = 0; bl < 32; bl++) {
        u64 a = 0ULL, b2 = 0ULL;
#pragma unroll
        for (int Q = 0; Q < 9; Q++) {
            ulonglong2 xv = *reinterpret_cast<const ulonglong2*>(&xsf[bl][4 * Q]);
            a  = fma2(xv.x, w[2 * Q],     a);
            b2 = fma2(xv.y, w[2 * Q + 1], b2);
        }
        float p, q, r, s;
        unpack2(a, p, q); unpack2(b2, r, s);
        crow[(size_t)bl * Hsz] = (p + q) + (r + s);
    }
}

// ============================================================
// Kernel 2: scan (float2, 65536 threads, 512 blocks).
// In-place exclusive scan over l + b_enc + ReLU.
// ============================================================
__global__ void __launch_bounds__(128) scan_kernel(
    const float* __restrict__ benc)    // [1, 512]
{
    const int g = blockIdx.x * 128 + threadIdx.x;   // 0..65535
    const int b = g >> 8;
    const int hp = g & 255;

    float2 be = *reinterpret_cast<const float2*>(&benc[2 * hp]);
    float2* p = reinterpret_cast<float2*>(g_c) + ((size_t)b * Hsz) / 2 + hp;
    const size_t stride = (size_t)Bsz * Hsz / 2;

    float ax = 0.f, ay = 0.f;
#pragma unroll 4
    for (int l = 0; l < Lsz; l++) {
        float2 v = p[l * stride];
        float2 o;
        o.x = fmaxf(ax + be.x, 0.f);
        o.y = fmaxf(ay + be.y, 0.f);
        p[l * stride] = o;
        ax += v.x; ay += v.y;
    }
}

// ============================================================
// Kernel 3: decoder, 4b x 10o per thread (40 fma2 : 9 LDS per k-pair).
// f32x2 lanes = k-pairs; h tiles double-buffered via cp.async;
// V register-prefetched into packed smem. grid (bq=2, l=500), block 128.
// ============================================================
__global__ void __launch_bounds__(128, 4) dec_kernel(
    const float* __restrict__ Vmu,   // [L, 512, 15]
    const float* __restrict__ bmu,   // [L, 1, 15]
    const float* __restrict__ Vsig,  // [L, 512, 15]
    const float* __restrict__ bsig,  // [L, 1, 15]
    const float* __restrict__ Vpi,   // [L, 512, 5]
    const float* __restrict__ bpi,   // [L, 1, 5]
    float* __restrict__ out)         // [B, L, 35]
{
    const int bq = blockIdx.x;       // b tile (128 b)
    const int l  = blockIdx.y;
    const int t  = threadIdx.x;
    const int ot = t & 3;            // 10 consecutive o
    const int bt = t >> 2;           // 0..31; b = bt + 32*ii, ii 0..3

    __shared__ __align__(16) u64 hsb[2][128][18];  // k-pairs raw, row=144B
    __shared__ __align__(16) u64 vsb[2][16][40];   // V k-pair packs, o padded

    // ---- V prefetch bookkeeping: 560 entries, 5 per thread ----
    const float* vptr[5];
    int vkkp[5], vo[5], vrow[5];
    bool vp[5];
#pragma unroll
    for (int j = 0; j < 5; j++) {
        int e = t + 128 * j;
        vp[j] = (e < 16 * 35);
        int kk = vp[j] ? e / 35 : 0;
        int o  = vp[j] ? e - kk * 35 : 0;
        vkkp[j] = kk; vo[j] = o;
        if (o < 15)      { vptr[j] = Vmu  + ((size_t)l * Hsz + 2 * kk) * 15 + o;        vrow[j] = 15; }
        else if (o < 30) { vptr[j] = Vsig + ((size_t)l * Hsz + 2 * kk) * 15 + (o - 15); vrow[j] = 15; }
        else             { vptr[j] = Vpi  + ((size_t)l * Hsz + 2 * kk) * 5  + (o - 30); vrow[j] = 5;  }
    }
    u64 vheld[5];
#define LDV()                                                        \
    do {                                                             \
        _Pragma("unroll")                                            \
        for (int j = 0; j < 5; j++)                                  \
            if (vp[j]) {                                             \
                vheld[j] = pack2(vptr[j][0], vptr[j][vrow[j]]);      \
                vptr[j] += 32 * vrow[j];                             \
            }                                                        \
    } while (0)
#define STV(bf)                                                      \
    do {                                                             \
        _Pragma("unroll")                                            \
        for (int j = 0; j < 5; j++)                                  \
            if (vp[j]) vsb[bf][vkkp[j]][vo[j]] = vheld[j];           \
    } while (0)

    const float* hbase = &g_c[((size_t)l * Bsz + bq * 128) * Hsz];
#define CPH(tile, bf)                                                     \
    do {                                                                  \
        const float* src_ = hbase + (tile) * 32;                         \
        _Pragma("unroll")                                                 \
        for (int n = 0; n < 8; n++) {                                     \
            int idx_ = t + 128 * n;                                       \
            int row_ = idx_ >> 3, ch_ = idx_ & 7;                         \
            cp_async16(smem_u32(&hsb[bf][row_][ch_ * 2]),                 \
                       src_ + (size_t)row_ * Hsz + ch_ * 4);              \
        }                                                                 \
        cp_commit();                                                      \
    } while (0)

    float bias[10];
#pragma unroll
    for (int j = 0; j < 10; j++) {
        int o = 10 * ot + j;
        bias[j] = (o < 15) ? bmu[l * 15 + o]
                : (o < 30) ? bsig[l * 15 + (o - 15)]
                : (o < 35) ? bpi[l * 5 + (o - 30)] : 0.f;
    }

    // ---- prolog ----
    LDV();              // V(0)
    STV(0);
    LDV();              // V(1) held
    CPH(0, 0);
    CPH(1, 1);

    u64 acc[4][10];
#pragma unroll
    for (int ii = 0; ii < 4; ii++)
#pragma unroll
        for (int j = 0; j < 10; j++) acc[ii][j] = 0ULL;

    for (int tl = 0; tl < 16; tl++) {
        if (tl < 15) cp_wait<1>(); else cp_wait<0>();
        __syncthreads();
        if (tl < 15) STV((tl + 1) & 1);
        if (tl < 14) LDV();          // V(tl+2)

        const int buf = tl & 1;
#pragma unroll
        for (int kk = 0; kk < 16; kk++) {
            u64 hv[4];
#pragma unroll
            for (int ii = 0; ii < 4; ii++) hv[ii] = hsb[buf][bt + 32 * ii][kk];
            u64 vv[10];
#pragma unroll
            for (int jq = 0; jq < 5; jq++) {
                ulonglong2 q2 = *reinterpret_cast<const ulonglong2*>(
                    &vsb[buf][kk][10 * ot + 2 * jq]);
                vv[2 * jq] = q2.x; vv[2 * jq + 1] = q2.y;
            }
#pragma unroll
            for (int ii = 0; ii < 4; ii++)
#pragma unroll
                for (int j = 0; j < 10; j++)
                    acc[ii][j] = fma2(hv[ii], vv[j], acc[ii][j]);
        }
        __syncthreads();
        if (tl < 14) CPH(tl + 2, buf);
    }

    // epilogue: horizontal add over k-pair lanes + bias
#pragma unroll
    for (int ii = 0; ii < 4; ii++) {
        int b = bq * 128 + bt + 32 * ii;
        float* op = &out[((size_t)b * Lsz + l) * OUTsz];
#pragma unroll
        for (int j = 0; j < 10; j++) {
            int o = 10 * ot + j;
            if (o < OUTsz) {
                float lo, hi;
                unpack2(acc[ii][j], lo, hi);
                op[o] = lo + hi + bias[j];
            }
        }
    }
#undef LDV
#undef STV
#undef CPH
}

extern "C" void kernel_launch(void* const* d_in, const int* in_sizes, int n_in,
                              void* d_out, int out_size) {
    (void)in_sizes; (void)n_in; (void)out_size;
    const float* inputs = (const float*)d_in[0];
    const float* z      = (const float*)d_in[1];
    const float* W_enc  = (const float*)d_in[2];
    const float* b_enc  = (const float*)d_in[3];
    const float* V_mu   = (const float*)d_in[4];
    const float* b_mu   = (const float*)d_in[5];
    const float* V_sig  = (const float*)d_in[6];
    const float* b_sig  = (const float*)d_in[7];
    const float* V_pi   = (const float*)d_in[8];
    const float* b_pi   = (const float*)d_in[9];
    float* out = (float*)d_out;

    enc_kernel<<<dim3(8, Lsz), 512>>>(inputs, z, W_enc);
    scan_kernel<<<(Bsz * Hsz / 2) / 128, 128>>>(b_enc);
    dec_kernel<<<dim3(2, Lsz), 128>>>(V_mu, b_mu, V_sig, b_sig, V_pi, b_pi, out);
}

// round 9
// speedup vs baseline: 1.1132x; 1.1132x over previous
#include <cuda_runtime.h>

typedef unsigned long long u64;

#define Bsz 256
#define Lsz 500
#define Hsz 512
#define Isz 35
#define OUTsz 35

// Scratch: encoder writes c[l][b][h]; scan converts IN-PLACE to
// h[l][b][h] = relu(b_enc + exclusive prefix); decoder reads it. 262 MB.
__device__ float g_c[(size_t)Lsz * Bsz * Hsz];

// ---- packed f32x2 helpers ----
__device__ __forceinline__ u64 fma2(u64 a, u64 b, u64 c) {
    u64 d;
    asm("fma.rn.f32x2 %0, %1, %2, %3;" : "=l"(d) : "l"(a), "l"(b), "l"(c));
    return d;
}
__device__ __forceinline__ u64 pack2(float x, float y) {
    u64 r;
    asm("mov.b64 %0, {%1, %2};" : "=l"(r) : "f"(x), "f"(y));
    return r;
}
__device__ __forceinline__ void unpack2(u64 v, float& x, float& y) {
    asm("mov.b64 {%0, %1}, %2;" : "=f"(x), "=f"(y) : "l"(v));
}
__device__ __forceinline__ unsigned smem_u32(const void* p) {
    return (unsigned)__cvta_generic_to_shared(p);
}
__device__ __forceinline__ void cp_async16(unsigned dst, const void* src) {
    asm volatile("cp.async.cg.shared.global [%0], [%1], 16;" ::
                 "r"(dst), "l"(src));
}
__device__ __forceinline__ void cp_commit() {
    asm volatile("cp.async.commit_group;");
}
template <int N>
__device__ __forceinline__ void cp_wait() {
    asm volatile("cp.async.wait_group %0;" :: "n"(N));
}

// ============================================================
// Kernel 1: encoder (R5 exact, measured 125 us x3).
// f32x2 lanes = i-pairs; W for 2 h columns in 72 regs, reused over 32 b;
// x broadcast via LDS.128 (1 wavefront serves 4 fma2).
// grid (bq=8, l=500), block 256.
// ============================================================
__global__ void __launch_bounds__(256, 2) enc_kernel(
    const float* __restrict__ inputs,  // [B, L, 3]
    const float* __restrict__ z,       // [B, L, 32]
    const float* __restrict__ W)       // [L, 35, 512]
{
    const int bq = blockIdx.x;   // b tile (32 b)
    const int l  = blockIdx.y;
    const int t  = threadIdx.x;

    __shared__ __align__(16) float xsf[32][36];   // i padded to 36, x[35]=0

    for (int idx = t; idx < 32 * 36; idx += 256) {
        int bl = idx / 36, i = idx - bl * 36;
        int b = bq * 32 + bl;
        float v = 0.f;
        if (i < 3)       v = inputs[(b * Lsz + l) * 3 + i];
        else if (i < 35) v = z[(b * Lsz + l) * 32 + (i - 3)];
        xsf[bl][i] = v;
    }

    u64 w0[18], w1[18];
    const float* Wl = W + (size_t)l * Isz * Hsz;
#pragma unroll
    for (int q = 0; q < 17; q++) {
        w0[q] = pack2(Wl[(2 * q) * Hsz + t],       Wl[(2 * q + 1) * Hsz + t]);
        w1[q] = pack2(Wl[(2 * q) * Hsz + t + 256], Wl[(2 * q + 1) * Hsz + t + 256]);
    }
    w0[17] = pack2(Wl[34 * Hsz + t], 0.f);
    w1[17] = pack2(Wl[34 * Hsz + t + 256], 0.f);
    __syncthreads();

    float* crow = &g_c[((size_t)l * Bsz + bq * 32) * Hsz];
    for (int bl = 0; bl < 32; bl++) {
        u64 a0 = 0ULL, b0 = 0ULL, a1 = 0ULL, b1 = 0ULL;
#pragma unroll
        for (int Q = 0; Q < 9; Q++) {
            ulonglong2 xv = *reinterpret_cast<const ulonglong2*>(&xsf[bl][4 * Q]);
            a0 = fma2(xv.x, w0[2 * Q],     a0);
            b0 = fma2(xv.y, w0[2 * Q + 1], b0);
            a1 = fma2(xv.x, w1[2 * Q],     a1);
            b1 = fma2(xv.y, w1[2 * Q + 1], b1);
        }
        float p, q, r, s;
        unpack2(a0, p, q); unpack2(b0, r, s);
        crow[(size_t)bl * Hsz + t] = (p + q) + (r + s);
        unpack2(a1, p, q); unpack2(b1, r, s);
        crow[(size_t)bl * Hsz + t + 256] = (p + q) + (r + s);
    }
}

// ============================================================
// Kernel 2: scan (float2, 65536 threads, 512 blocks).
// In-place exclusive scan over l + b_enc + ReLU.
// ============================================================
__global__ void __launch_bounds__(128) scan_kernel(
    const float* __restrict__ benc)    // [1, 512]
{
    const int g = blockIdx.x * 128 + threadIdx.x;   // 0..65535
    const int b = g >> 8;
    const int hp = g & 255;

    float2 be = *reinterpret_cast<const float2*>(&benc[2 * hp]);
    float2* p = reinterpret_cast<float2*>(g_c) + ((size_t)b * Hsz) / 2 + hp;
    const size_t stride = (size_t)Bsz * Hsz / 2;

    float ax = 0.f, ay = 0.f;
#pragma unroll 4
    for (int l = 0; l < Lsz; l++) {
        float2 v = p[l * stride];
        float2 o;
        o.x = fmaxf(ax + be.x, 0.f);
        o.y = fmaxf(ay + be.y, 0.f);
        p[l * stride] = o;
        ax += v.x; ay += v.y;
    }
}

// ============================================================
// Kernel 3: decoder (R8 exact, ~158 us by subtraction).
// 4b x 10o per thread (40 fma2 : 9 LDS per k-pair); k-pair lanes;
// h double-buffered via cp.async; V register-prefetched.
// grid (bq=2, l=500), block 128.
// ============================================================
__global__ void __launch_bounds__(128, 4) dec_kernel(
    const float* __restrict__ Vmu,   // [L, 512, 15]
    const float* __restrict__ bmu,   // [L, 1, 15]
    const float* __restrict__ Vsig,  // [L, 512, 15]
    const float* __restrict__ bsig,  // [L, 1, 15]
    const float* __restrict__ Vpi,   // [L, 512, 5]
    const float* __restrict__ bpi,   // [L, 1, 5]
    float* __restrict__ out)         // [B, L, 35]
{
    const int bq = blockIdx.x;       // b tile (128 b)
    const int l  = blockIdx.y;
    const int t  = threadIdx.x;
    const int ot = t & 3;            // 10 consecutive o
    const int bt = t >> 2;           // 0..31; b = bt + 32*ii, ii 0..3

    __shared__ __align__(16) u64 hsb[2][128][18];  // k-pairs raw, row=144B
    __shared__ __align__(16) u64 vsb[2][16][40];   // V k-pair packs, o padded

    const float* vptr[5];
    int vkkp[5], vo[5], vrow[5];
    bool vp[5];
#pragma unroll
    for (int j = 0; j < 5; j++) {
        int e = t + 128 * j;
        vp[j] = (e < 16 * 35);
        int kk = vp[j] ? e / 35 : 0;
        int o  = vp[j] ? e - kk * 35 : 0;
        vkkp[j] = kk; vo[j] = o;
        if (o < 15)      { vptr[j] = Vmu  + ((size_t)l * Hsz + 2 * kk) * 15 + o;        vrow[j] = 15; }
        else if (o < 30) { vptr[j] = Vsig + ((size_t)l * Hsz + 2 * kk) * 15 + (o - 15); vrow[j] = 15; }
        else             { vptr[j] = Vpi  + ((size_t)l * Hsz + 2 * kk) * 5  + (o - 30); vrow[j] = 5;  }
    }
    u64 vheld[5];
#define LDV()                                                        \
    do {                                                             \
        _Pragma("unroll")                                            \
        for (int j = 0; j < 5; j++)                                  \
            if (vp[j]) {                                             \
                vheld[j] = pack2(vptr[j][0], vptr[j][vrow[j]]);      \
                vptr[j] += 32 * vrow[j];                             \
            }                                                        \
    } while (0)
#define STV(bf)                                                      \
    do {                                                             \
        _Pragma("unroll")                                            \
        for (int j = 0; j < 5; j++)                                  \
            if (vp[j]) vsb[bf][vkkp[j]][vo[j]] = vheld[j];           \
    } while (0)

    const float* hbase = &g_c[((size_t)l * Bsz + bq * 128) * Hsz];
#define CPH(tile, bf)                                                     \
    do {                                                                  \
        const float* src_ = hbase + (tile) * 32;                         \
        _Pragma("unroll")                                                 \
        for (int n = 0; n < 8; n++) {                                     \
            int idx_ = t + 128 * n;                                       \
            int row_ = idx_ >> 3, ch_ = idx_ & 7;                         \
            cp_async16(smem_u32(&hsb[bf][row_][ch_ * 2]),                 \
                       src_ + (size_t)row_ * Hsz + ch_ * 4);              \
        }                                                                 \
        cp_commit();                                                      \
    } while (0)

    float bias[10];
#pragma unroll
    for (int j = 0; j < 10; j++) {
        int o = 10 * ot + j;
        bias[j] = (o < 15) ? bmu[l * 15 + o]
                : (o < 30) ? bsig[l * 15 + (o - 15)]
                : (o < 35) ? bpi[l * 5 + (o - 30)] : 0.f;
    }

    LDV();              // V(0)
    STV(0);
    LDV();              // V(1) held
    CPH(0, 0);
    CPH(1, 1);

    u64 acc[4][10];
#pragma unroll
    for (int ii = 0; ii < 4; ii++)
#pragma unroll
        for (int j = 0; j < 10; j++) acc[ii][j] = 0ULL;

    for (int tl = 0; tl < 16; tl++) {
        if (tl < 15) cp_wait<1>(); else cp_wait<0>();
        __syncthreads();
        if (tl < 15) STV((tl + 1) & 1);
        if (tl < 14) LDV();          // V(tl+2)

        const int buf = tl & 1;
#pragma unroll
        for (int kk = 0; kk < 16; kk++) {
            u64 hv[4];
#pragma unroll
            for (int ii = 0; ii < 4; ii++) hv[ii] = hsb[buf][bt + 32 * ii][kk];
            u64 vv[10];
#pragma unroll
            for (int jq = 0; jq < 5; jq++) {
                ulonglong2 q2 = *reinterpret_cast<const ulonglong2*>(
                    &vsb[buf][kk][10 * ot + 2 * jq]);
                vv[2 * jq] = q2.x; vv[2 * jq + 1] = q2.y;
            }
#pragma unroll
            for (int ii = 0; ii < 4; ii++)
#pragma unroll
                for (int j = 0; j < 10; j++)
                    acc[ii][j] = fma2(hv[ii], vv[j], acc[ii][j]);
        }
        __syncthreads();
        if (tl < 14) CPH(tl + 2, buf);
    }

#pragma unroll
    for (int ii = 0; ii < 4; ii++) {
        int b = bq * 128 + bt + 32 * ii;
        float* op = &out[((size_t)b * Lsz + l) * OUTsz];
#pragma unroll
        for (int j = 0; j < 10; j++) {
            int o = 10 * ot + j;
            if (o < OUTsz) {
                float lo, hi;
                unpack2(acc[ii][j], lo, hi);
                op[o] = lo + hi + bias[j];
            }
        }
    }
#undef LDV
#undef STV
#undef CPH
}

extern "C" void kernel_launch(void* const* d_in, const int* in_sizes, int n_in,
                              void* d_out, int out_size) {
    (void)in_sizes; (void)n_in; (void)out_size;
    const float* inputs = (const float*)d_in[0];
    const float* z      = (const float*)d_in[1];
    const float* W_enc  = (const float*)d_in[2];
    const float* b_enc  = (const float*)d_in[3];
    const float* V_mu   = (const float*)d_in[4];
    const float* b_mu   = (const float*)d_in[5];
    const float* V_sig  = (const float*)d_in[6];
    const float* b_sig  = (const float*)d_in[7];
    const float* V_pi   = (const float*)d_in[8];
    const float* b_pi   = (const float*)d_in[9];
    float* out = (float*)d_out;

    enc_kernel<<<dim3(8, Lsz), 256>>>(inputs, z, W_enc);
    scan_kernel<<<(Bsz * Hsz / 2) / 128, 128>>>(b_enc);
    dec_kernel<<<dim3(2, Lsz), 128>>>(V_mu, b_mu, V_sig, b_sig, V_pi, b_pi, out);
}